// round 1
// baseline (speedup 1.0000x reference)
#include <cuda_runtime.h>
#include <math.h>

#define HID   128
#define KPF   9                  // k-rows per input feature: 1 silu + 8 spline
#define KTOT  (HID * KPF)        // 1152
#define CH_F  8                  // features per K-chunk
#define CH_K  (CH_F * KPF)       // 72
#define BM    128                // rows per block (layer GEMM)
#define NMAX  131072
#define KPMAX 256

// ---------------- scratch (device globals; no allocation allowed) ----------
__device__ float g_Wc1[KTOT * HID];
__device__ float g_Wc2[KTOT * HID];
__device__ float g_h[(size_t)NMAX * HID];
__device__ float g_pn[KPMAX * HID];

// ---------------- weight prep: Wc[(i*9+slot)*128 + o] ----------------------
__global__ void prep_w_kernel(const float* __restrict__ bw,
                              const float* __restrict__ sw,
                              const float* __restrict__ sc,
                              float* __restrict__ Wc)
{
    int idx = blockIdx.x * 256 + threadIdx.x;   // over (i,o) pairs
    if (idx >= HID * HID) return;
    int i = idx / HID, o = idx % HID;
    Wc[(i * KPF) * HID + o] = bw[o * HID + i];
    float s = sc[o * HID + i];
#pragma unroll
    for (int c = 0; c < 8; ++c)
        Wc[(i * KPF + 1 + c) * HID + o] = sw[(o * HID + i) * 8 + c] * s;
}

// ---------------- prototype normalization ----------------------------------
__global__ void prep_p_kernel(const float* __restrict__ P, float* __restrict__ Pn)
{
    int r = blockIdx.x;
    int t = threadIdx.x;          // 128 threads
    float v = P[r * HID + t];
    float s = v * v;
#pragma unroll
    for (int o = 16; o > 0; o >>= 1) s += __shfl_xor_sync(0xffffffffu, s, o);
    __shared__ float red[4];
    if ((t & 31) == 0) red[t >> 5] = s;
    __syncthreads();
    float tot = red[0] + red[1] + red[2] + red[3];
    float nrm = fmaxf(sqrtf(tot), 1e-8f);
    Pn[r * HID + t] = v / nrm;
}

// ---------------- fused KAN layer: Y = A(X) @ Wc ----------------------------
// A(X) rows: per feature i -> [silu(x_i), B0..B7(x_i)]  (cubic B-splines)
__global__ void __launch_bounds__(256, 1) layer_kernel(
    const float* __restrict__ X, const float* __restrict__ Wc,
    const float* __restrict__ grid, float* __restrict__ Y)
{
    extern __shared__ float sm[];
    float* sX   = sm;                    // BM*HID    = 16384 f
    float* sA   = sX + BM * HID;         // CH_K*BM   = 9216 f   [kk][row]
    float* sW   = sA + CH_K * BM;        // CH_K*HID  = 9216 f   [kk][o]
    float* sg   = sW + CH_K * HID;       // 16 f (12 used)
    float* sinv = sg + 16;               // 32 f (30 used): p=1 @0, p=2 @11, p=3 @21

    const int tid = threadIdx.x;
    const size_t row0 = (size_t)blockIdx.x * BM;

    if (tid < 12) sg[tid] = grid[tid];
    __syncthreads();
    if (tid < 30) {
        int p, j;
        if (tid < 11)      { p = 1; j = tid; }
        else if (tid < 21) { p = 2; j = tid - 11; }
        else               { p = 3; j = tid - 21; }
        sinv[tid] = 1.0f / (sg[j + p] - sg[j]);
    }
    // X tile (coalesced float4)
    {
        const float4* Xv = (const float4*)(X + row0 * HID);
        float4* sXv = (float4*)sX;
#pragma unroll
        for (int it = 0; it < (BM * HID / 4) / 256; ++it)
            sXv[tid + it * 256] = Xv[tid + it * 256];
    }
    __syncthreads();

    float acc[8][8];
#pragma unroll
    for (int r = 0; r < 8; ++r)
#pragma unroll
        for (int c = 0; c < 8; ++c) acc[r][c] = 0.0f;

    const int ty = tid >> 4, tx = tid & 15;

    for (int cc = 0; cc < HID / CH_F; ++cc) {
        // ---- W chunk
        {
            const float4* Wv = (const float4*)(Wc + (size_t)cc * CH_K * HID);
            float4* sWv = (float4*)sW;
#pragma unroll
            for (int it = 0; it < (CH_K * HID / 4) / 256; ++it)
                sWv[tid + it * 256] = Wv[tid + it * 256];
        }
        // ---- A chunk: 8 features x 128 rows, 4 tasks/thread
#pragma unroll
        for (int it = 0; it < (CH_F * BM) / 256; ++it) {
            int t = tid + it * 256;
            int f = t >> 7;            // 0..7
            int r = t & (BM - 1);      // 0..127
            float x = sX[r * HID + cc * CH_F + f];
            float silu = x / (1.0f + __expf(-x));
            float b[11];
#pragma unroll
            for (int j = 0; j < 11; ++j)
                b[j] = (x >= sg[j] && x < sg[j + 1]) ? 1.0f : 0.0f;
#pragma unroll
            for (int p = 1; p <= 3; ++p) {
                const float* inv = sinv + (p == 1 ? 0 : (p == 2 ? 11 : 21));
#pragma unroll
                for (int j = 0; j + p <= 10; ++j)
                    b[j] = (x - sg[j]) * inv[j] * b[j]
                         + (sg[j + p + 1] - x) * inv[j + 1] * b[j + 1];
            }
            float* dst = sA + f * KPF * BM + r;
            dst[0] = silu;
#pragma unroll
            for (int c = 0; c < 8; ++c) dst[(1 + c) * BM] = b[c];
        }
        __syncthreads();
        // ---- 128x128 FMA over 72 k-rows
#pragma unroll 8
        for (int kk = 0; kk < CH_K; ++kk) {
            float4 a0 = *(const float4*)(sA + kk * BM + ty * 8);
            float4 a1 = *(const float4*)(sA + kk * BM + ty * 8 + 4);
            float4 w0 = *(const float4*)(sW + kk * HID + tx * 8);
            float4 w1 = *(const float4*)(sW + kk * HID + tx * 8 + 4);
            float a[8] = {a0.x, a0.y, a0.z, a0.w, a1.x, a1.y, a1.z, a1.w};
            float w[8] = {w0.x, w0.y, w0.z, w0.w, w1.x, w1.y, w1.z, w1.w};
#pragma unroll
            for (int r = 0; r < 8; ++r)
#pragma unroll
                for (int c = 0; c < 8; ++c)
                    acc[r][c] += a[r] * w[c];
        }
        __syncthreads();
    }
#pragma unroll
    for (int r = 0; r < 8; ++r) {
        float* yr = Y + (row0 + ty * 8 + r) * HID + tx * 8;
        *(float4*)(yr)     = make_float4(acc[r][0], acc[r][1], acc[r][2], acc[r][3]);
        *(float4*)(yr + 4) = make_float4(acc[r][4], acc[r][5], acc[r][6], acc[r][7]);
    }
}

// ---------------- argmax of dot(e, pn) (== argmax cosine sim) ---------------
#define AR 64
#define AC 64
__global__ void __launch_bounds__(256, 1) assign_kernel(
    const float* __restrict__ E, const float* __restrict__ Pn,
    int Kp, float* __restrict__ outA)
{
    extern __shared__ float sm[];
    float* sE   = sm;               // AR*HID
    float* sP   = sE + AR * HID;    // AC*HID (xor-swizzled rows)
    float* sVal = sP + AC * HID;    // AR*16
    int*   sIdx = (int*)(sVal + AR * 16);

    const int tid = threadIdx.x;
    const size_t row0 = (size_t)blockIdx.x * AR;
    const int ty = tid >> 4, tx = tid & 15;

    {   // E tile, coalesced, row-major
        const float4* Ev = (const float4*)(E + row0 * HID);
        float4* sEv = (float4*)sE;
#pragma unroll
        for (int it = 0; it < (AR * HID / 4) / 256; ++it)
            sEv[tid + it * 256] = Ev[tid + it * 256];
    }

    float best[4]; int bidx[4];
#pragma unroll
    for (int r = 0; r < 4; ++r) { best[r] = -3.0e38f; bidx[r] = 0; }

    const int sws = (tx & 7) << 2;    // load swizzle: proto p = tx*4+c -> p>>2 == tx

    for (int pc = 0; pc < Kp / AC; ++pc) {
        __syncthreads();
        // proto chunk: lanes vary proto, xor-swizzle k within row
#pragma unroll
        for (int it = 0; it < (AC * HID / 4) / 256; ++it) {
            int t  = tid + it * 256;
            int p  = t & (AC - 1);
            int j4 = t >> 6;           // 0..31
            int k0 = j4 << 2;
            float4 v = *(const float4*)(Pn + (size_t)(pc * AC + p) * HID + k0);
            int sw = ((p >> 2) & 7) << 2;
            *(float4*)(sP + p * HID + (k0 ^ sw)) = v;
        }
        __syncthreads();

        float acc[4][4];
#pragma unroll
        for (int r = 0; r < 4; ++r)
#pragma unroll
            for (int c = 0; c < 4; ++c) acc[r][c] = 0.0f;

#pragma unroll 4
        for (int k = 0; k < HID; k += 4) {
            float4 a[4], pv[4];
#pragma unroll
            for (int r = 0; r < 4; ++r)
                a[r] = *(const float4*)(sE + (ty * 4 + r) * HID + k);
#pragma unroll
            for (int c = 0; c < 4; ++c)
                pv[c] = *(const float4*)(sP + (tx * 4 + c) * HID + (k ^ sws));
#pragma unroll
            for (int r = 0; r < 4; ++r)
#pragma unroll
                for (int c = 0; c < 4; ++c)
                    acc[r][c] += a[r].x * pv[c].x + a[r].y * pv[c].y
                               + a[r].z * pv[c].z + a[r].w * pv[c].w;
        }
#pragma unroll
        for (int c = 0; c < 4; ++c) {
            int idx = pc * AC + tx * 4 + c;
#pragma unroll
            for (int r = 0; r < 4; ++r)
                if (acc[r][c] > best[r]) { best[r] = acc[r][c]; bidx[r] = idx; }
        }
    }
    __syncthreads();
#pragma unroll
    for (int r = 0; r < 4; ++r) {
        sVal[(ty * 4 + r) * 16 + tx] = best[r];
        sIdx[(ty * 4 + r) * 16 + tx] = bidx[r];
    }
    __syncthreads();
    if (tid < AR) {
        float bv = -3.0e38f; int bi = 0x7fffffff;
#pragma unroll
        for (int t = 0; t < 16; ++t) {
            float v = sVal[tid * 16 + t];
            int   i = sIdx[tid * 16 + t];
            if (v > bv || (v == bv && i < bi)) { bv = v; bi = i; }
        }
        outA[row0 + tid] = (float)bi;   // lowest-index tie-break, jnp.argmax semantics
    }
}

// ---------------- launch ----------------------------------------------------
extern "C" void kernel_launch(void* const* d_in, const int* in_sizes, int n_in,
                              void* d_out, int out_size)
{
    const float* x    = (const float*)d_in[0];
    const float* prot = (const float*)d_in[1];
    const float* grid = (const float*)d_in[2];
    const float* bw1  = (const float*)d_in[3];
    const float* sw1  = (const float*)d_in[4];
    const float* sc1  = (const float*)d_in[5];
    const float* bw2  = (const float*)d_in[6];
    const float* sw2  = (const float*)d_in[7];
    const float* sc2  = (const float*)d_in[8];
    float* out = (float*)d_out;

    const int N  = in_sizes[0] / HID;   // 131072
    const int Kp = in_sizes[1] / HID;   // 256

    float *Wc1, *Wc2, *h, *pn;
    cudaGetSymbolAddress((void**)&Wc1, g_Wc1);
    cudaGetSymbolAddress((void**)&Wc2, g_Wc2);
    cudaGetSymbolAddress((void**)&h,   g_h);
    cudaGetSymbolAddress((void**)&pn,  g_pn);

    const int SMEM_LAYER  = (BM * HID + CH_K * BM + CH_K * HID + 48) * 4;     // ~139.5 KB
    const int SMEM_ASSIGN = (AR * HID + AC * HID + AR * 16 + AR * 16) * 4;    // 72 KB
    cudaFuncSetAttribute(layer_kernel,  cudaFuncAttributeMaxDynamicSharedMemorySize, SMEM_LAYER);
    cudaFuncSetAttribute(assign_kernel, cudaFuncAttributeMaxDynamicSharedMemorySize, SMEM_ASSIGN);

    prep_w_kernel<<<(HID * HID + 255) / 256, 256>>>(bw1, sw1, sc1, Wc1);
    prep_w_kernel<<<(HID * HID + 255) / 256, 256>>>(bw2, sw2, sc2, Wc2);
    prep_p_kernel<<<Kp, HID>>>(prot, pn);

    layer_kernel<<<N / BM, 256, SMEM_LAYER>>>(x, Wc1, grid, h);
    layer_kernel<<<N / BM, 256, SMEM_LAYER>>>(h, Wc2, grid, out);

    if ((size_t)out_size >= (size_t)N * HID + (size_t)N)
        assign_kernel<<<N / AR, 256, SMEM_ASSIGN>>>(out, pn, Kp, out + (size_t)N * HID);
}